// round 1
// baseline (speedup 1.0000x reference)
#include <cuda_runtime.h>
#include <math.h>
#include <stdint.h>

// Problem constants
#define B 8
#define A 100000
#define M 32
#define C 80
#define APB 256                      // anchors per block (one thread per anchor)
#define NTILES ((A + APB - 1) / APB) // 391

// Per-image accumulators (device globals — no allocation allowed)
__device__ double g_cls_sum[B];
__device__ double g_reg_sum[B];
__device__ int    g_num_pos[B];

__global__ void fl_init_kernel() {
    int i = threadIdx.x;
    if (i < B) {
        g_cls_sum[i] = 0.0;
        g_reg_sum[i] = 0.0;
        g_num_pos[i] = 0;
    }
}

__global__ __launch_bounds__(APB) void fl_main_kernel(
    const float* __restrict__ cls,      // [B, A, C]
    const float* __restrict__ reg,      // [B, A, 4]
    const float* __restrict__ anchors,  // [1, A, 4]
    const float* __restrict__ ann)      // [B, M, 6]
{
    __shared__ float s_ann[M * 6];
    __shared__ signed char s_state[APB];  // 0 = ignore, 1 = neg, 2 = pos
    __shared__ short s_cid[APB];          // assigned class id (valid when pos)
    __shared__ float s_rc[APB / 32];      // per-warp cls partials
    __shared__ float s_rr[APB / 32];      // per-warp reg partials
    __shared__ int   s_rp[APB / 32];      // per-warp pos counts

    const int b   = blockIdx.y;
    const int a0  = blockIdx.x * APB;
    const int tid = threadIdx.x;

    // Stage annotations for this image
    if (tid < M * 6) s_ann[tid] = ann[b * (M * 6) + tid];
    __syncthreads();

    float reg_partial = 0.0f;
    int   pos_cnt = 0;

    const int a = a0 + tid;
    if (a < A) {
        const float ax1 = anchors[a * 4 + 0];
        const float ay1 = anchors[a * 4 + 1];
        const float ax2 = anchors[a * 4 + 2];
        const float ay2 = anchors[a * 4 + 3];
        const float aw = ax2 - ax1;
        const float ah = ay2 - ay1;
        const float area_a = aw * ah;

        // IoU max / argmax over M ground-truth boxes (first-max tie-break,
        // matching jnp.argmax semantics).
        float best = -1e30f;
        int   bi = 0;
        #pragma unroll 8
        for (int j = 0; j < M; j++) {
            const float gx1 = s_ann[j * 6 + 0];
            const float gy1 = s_ann[j * 6 + 1];
            const float gx2 = s_ann[j * 6 + 2];
            const float gy2 = s_ann[j * 6 + 3];
            const float gcl = s_ann[j * 6 + 4];
            const float iw = fminf(ax2, gx2) - fmaxf(ax1, gx1);
            const float ih = fminf(ay2, gy2) - fmaxf(ay1, gy1);
            const float inter = fmaxf(iw, 0.0f) * fmaxf(ih, 0.0f);
            const float ua = fmaxf(area_a + (gx2 - gx1) * (gy2 - gy1) - inter, 1e-8f);
            float iou = inter / ua;
            if (gcl == -1.0f) iou = -1.0f;  // padding mask per reference
            if (iou > best) { best = iou; bi = j; }
        }

        const bool pos = (best >= 0.5f);
        s_state[tid] = pos ? (signed char)2 : (best < 0.4f ? (signed char)1 : (signed char)0);
        s_cid[tid]   = (short)(int)s_ann[bi * 6 + 4];

        if (pos) {
            pos_cnt = 1;
            // Regression loss (smooth L1) for this positive anchor
            const float gx1 = s_ann[bi * 6 + 0];
            const float gy1 = s_ann[bi * 6 + 1];
            const float gx2 = s_ann[bi * 6 + 2];
            const float gy2 = s_ann[bi * 6 + 3];
            float gw = gx2 - gx1;
            float gh = gy2 - gy1;
            const float gcx = gx1 + 0.5f * gw;
            const float gcy = gy1 + 0.5f * gh;
            gw = fmaxf(gw, 1.0f);
            gh = fmaxf(gh, 1.0f);
            const float acx = ax1 + 0.5f * aw;
            const float acy = ay1 + 0.5f * ah;

            const float t0 = ((gcx - acx) / aw) * 10.0f;       // /0.1
            const float t1 = ((gcy - acy) / ah) * 10.0f;       // /0.1
            const float t2 = logf(gw / aw) * 5.0f;             // /0.2
            const float t3 = logf(gh / ah) * 5.0f;             // /0.2

            const float4 r = *reinterpret_cast<const float4*>(reg + ((size_t)b * A + a) * 4);
            const float d0 = fabsf(t0 - r.x);
            const float d1 = fabsf(t1 - r.y);
            const float d2 = fabsf(t2 - r.z);
            const float d3 = fabsf(t3 - r.w);
            const float th = 1.0f / 9.0f;
            const float c2 = 0.5f / 9.0f;
            float rl = 0.0f;
            rl += (d0 <= th) ? 4.5f * d0 * d0 : d0 - c2;
            rl += (d1 <= th) ? 4.5f * d1 * d1 : d1 - c2;
            rl += (d2 <= th) ? 4.5f * d2 * d2 : d2 - c2;
            rl += (d3 <= th) ? 4.5f * d3 * d3 : d3 - c2;
            reg_partial = rl;
        }
    } else {
        s_state[tid] = 0;
        s_cid[tid] = -1;
    }
    __syncthreads();

    // Phase 2: coalesced sweep of the classification block for this tile.
    float cls_partial = 0.0f;
    {
        const int nA = min(APB, A - a0);
        const int total = nA * C;
        const float* __restrict__ cp = cls + ((size_t)b * A + a0) * C;
        for (int e = tid; e < total; e += APB) {
            const int al = e / C;
            const int st = (int)s_state[al];
            if (st == 0) continue;  // ignored anchor -> zero loss, skip load
            float p = cp[e];
            p = fminf(fmaxf(p, 1e-4f), 1.0f - 1e-4f);
            float loss;
            if (st == 2 && (e - al * C) == (int)s_cid[al]) {
                const float q = 1.0f - p;
                loss = 0.25f * q * q * (-__logf(p));
            } else {
                loss = 0.75f * p * p * (-__logf(1.0f - p));
            }
            cls_partial += loss;
        }
    }

    // Block reduction -> per-image double accumulators
    float cv = cls_partial;
    float rv = reg_partial;
    int   pv = pos_cnt;
    #pragma unroll
    for (int o = 16; o > 0; o >>= 1) {
        cv += __shfl_down_sync(0xFFFFFFFFu, cv, o);
        rv += __shfl_down_sync(0xFFFFFFFFu, rv, o);
        pv += __shfl_down_sync(0xFFFFFFFFu, pv, o);
    }
    const int wid = tid >> 5;
    const int lane = tid & 31;
    if (lane == 0) { s_rc[wid] = cv; s_rr[wid] = rv; s_rp[wid] = pv; }
    __syncthreads();
    if (tid == 0) {
        float c = 0.0f, r = 0.0f;
        int p = 0;
        #pragma unroll
        for (int i = 0; i < APB / 32; i++) { c += s_rc[i]; r += s_rr[i]; p += s_rp[i]; }
        atomicAdd(&g_cls_sum[b], (double)c);
        atomicAdd(&g_reg_sum[b], (double)r);
        if (p) atomicAdd(&g_num_pos[b], p);
    }
}

__global__ void fl_finalize_kernel(float* __restrict__ out) {
    if (threadIdx.x == 0) {
        double cl = 0.0, rl = 0.0;
        #pragma unroll
        for (int b = 0; b < B; b++) {
            const int np = g_num_pos[b];
            const double d = (np < 1) ? 1.0 : (double)np;
            cl += g_cls_sum[b] / d;
            if (np > 0) rl += g_reg_sum[b] / (4.0 * d);
        }
        out[0] = (float)(cl / (double)B);
        out[1] = (float)(rl / (double)B);
    }
}

extern "C" void kernel_launch(void* const* d_in, const int* in_sizes, int n_in,
                              void* d_out, int out_size) {
    // Match inputs by element count (robust to ordering).
    const float* cls = nullptr;
    const float* reg = nullptr;
    const float* anc = nullptr;
    const float* ann = nullptr;
    for (int i = 0; i < n_in; i++) {
        switch (in_sizes[i]) {
            case B * A * C:  cls = (const float*)d_in[i]; break;  // 64,000,000
            case B * A * 4:  reg = (const float*)d_in[i]; break;  //  3,200,000
            case A * 4:      anc = (const float*)d_in[i]; break;  //    400,000
            case B * M * 6:  ann = (const float*)d_in[i]; break;  //      1,536
            default: break;
        }
    }
    float* out = (float*)d_out;

    fl_init_kernel<<<1, 32>>>();
    dim3 grid(NTILES, B);
    fl_main_kernel<<<grid, APB>>>(cls, reg, anc, ann);
    fl_finalize_kernel<<<1, 32>>>(out);
}

// round 2
// speedup vs baseline: 2.2364x; 2.2364x over previous
#include <cuda_runtime.h>
#include <math.h>
#include <stdint.h>

// Problem constants
#define B 8
#define A 100000
#define M 32
#define C 80
#define APB 256                      // anchors per block (one thread per anchor)
#define NTILES ((A + APB - 1) / APB) // 391
#define V4PA (C / 4)                 // float4 per anchor = 20

// Per-image accumulators (device globals — no allocation allowed)
__device__ double g_cls_sum[B];
__device__ double g_reg_sum[B];
__device__ int    g_num_pos[B];

__global__ void fl_init_kernel() {
    int i = threadIdx.x;
    if (i < B) {
        g_cls_sum[i] = 0.0;
        g_reg_sum[i] = 0.0;
        g_num_pos[i] = 0;
    }
}

// negative focal term (before the 0.75 weight): p^2 * (-log(1-p)), p clamped
__device__ __forceinline__ float neg_term(float p) {
    p = fminf(fmaxf(p, 1e-4f), 1.0f - 1e-4f);
    return p * p * (-__logf(1.0f - p));
}

__global__ __launch_bounds__(APB) void fl_main_kernel(
    const float* __restrict__ cls,      // [B, A, C]
    const float* __restrict__ reg,      // [B, A, 4]
    const float* __restrict__ anchors,  // [1, A, 4]
    const float* __restrict__ ann)      // [B, M, 6]
{
    __shared__ float s_ann[M * 6];
    __shared__ float s_mask[APB];         // 0.75 if anchor contributes neg terms, else 0
    __shared__ float s_rc[APB / 32];
    __shared__ float s_rr[APB / 32];
    __shared__ int   s_rp[APB / 32];

    const int b   = blockIdx.y;
    const int a0  = blockIdx.x * APB;
    const int tid = threadIdx.x;

    if (tid < M * 6) s_ann[tid] = ann[b * (M * 6) + tid];
    __syncthreads();

    float reg_partial = 0.0f;
    float cls_partial = 0.0f;
    int   pos_cnt = 0;

    const int a = a0 + tid;
    if (a < A) {
        const float ax1 = anchors[a * 4 + 0];
        const float ay1 = anchors[a * 4 + 1];
        const float ax2 = anchors[a * 4 + 2];
        const float ay2 = anchors[a * 4 + 3];
        const float aw = ax2 - ax1;
        const float ah = ay2 - ay1;
        const float area_a = aw * ah;

        // IoU max / argmax over M GT boxes (first-max tie-break = jnp.argmax)
        float best = -1e30f;
        int   bi = 0;
        #pragma unroll 8
        for (int j = 0; j < M; j++) {
            const float gx1 = s_ann[j * 6 + 0];
            const float gy1 = s_ann[j * 6 + 1];
            const float gx2 = s_ann[j * 6 + 2];
            const float gy2 = s_ann[j * 6 + 3];
            const float gcl = s_ann[j * 6 + 4];
            const float iw = fminf(ax2, gx2) - fmaxf(ax1, gx1);
            const float ih = fminf(ay2, gy2) - fmaxf(ay1, gy1);
            const float inter = fmaxf(iw, 0.0f) * fmaxf(ih, 0.0f);
            const float ua = fmaxf(area_a + (gx2 - gx1) * (gy2 - gy1) - inter, 1e-8f);
            float iou = inter / ua;
            if (gcl == -1.0f) iou = -1.0f;
            if (iou > best) { best = iou; bi = j; }
        }

        const bool pos = (best >= 0.5f);
        const bool ign = (!pos) && (best >= 0.4f);
        s_mask[tid] = ign ? 0.0f : 0.75f;

        if (pos) {
            pos_cnt = 1;
            const float gx1 = s_ann[bi * 6 + 0];
            const float gy1 = s_ann[bi * 6 + 1];
            const float gx2 = s_ann[bi * 6 + 2];
            const float gy2 = s_ann[bi * 6 + 3];

            // ---- positive-class correction for the cls loss ----
            const int cid = (int)s_ann[bi * 6 + 4];
            float p = cls[((size_t)b * A + a) * C + cid];
            p = fminf(fmaxf(p, 1e-4f), 1.0f - 1e-4f);
            const float q = 1.0f - p;
            cls_partial += 0.25f * q * q * (-__logf(p))
                         - 0.75f * p * p * (-__logf(q));

            // ---- regression loss (smooth L1) ----
            float gw = gx2 - gx1;
            float gh = gy2 - gy1;
            const float gcx = gx1 + 0.5f * gw;
            const float gcy = gy1 + 0.5f * gh;
            gw = fmaxf(gw, 1.0f);
            gh = fmaxf(gh, 1.0f);
            const float acx = ax1 + 0.5f * aw;
            const float acy = ay1 + 0.5f * ah;

            const float t0 = ((gcx - acx) / aw) * 10.0f;
            const float t1 = ((gcy - acy) / ah) * 10.0f;
            const float t2 = logf(gw / aw) * 5.0f;
            const float t3 = logf(gh / ah) * 5.0f;

            const float4 r = *reinterpret_cast<const float4*>(reg + ((size_t)b * A + a) * 4);
            const float d0 = fabsf(t0 - r.x);
            const float d1 = fabsf(t1 - r.y);
            const float d2 = fabsf(t2 - r.z);
            const float d3 = fabsf(t3 - r.w);
            const float th = 1.0f / 9.0f;
            const float c2 = 0.5f / 9.0f;
            float rl = 0.0f;
            rl += (d0 <= th) ? 4.5f * d0 * d0 : d0 - c2;
            rl += (d1 <= th) ? 4.5f * d1 * d1 : d1 - c2;
            rl += (d2 <= th) ? 4.5f * d2 * d2 : d2 - c2;
            rl += (d3 <= th) ? 4.5f * d3 * d3 : d3 - c2;
            reg_partial = rl;
        }
    } else {
        s_mask[tid] = 0.0f;
    }
    __syncthreads();

    // Phase 2: branch-free vectorized sweep of the tile's class block.
    // Tile = [nA, 80] floats = [nA, 20] float4 (float4 never crosses anchors).
    {
        const int nA = min(APB, A - a0);
        const float4* __restrict__ cp4 =
            reinterpret_cast<const float4*>(cls + ((size_t)b * A + a0) * C);

        if (nA == APB) {
            // Hot path: fixed trip count, no predicates -> max MLP
            #pragma unroll
            for (int k = 0; k < V4PA; k++) {
                const int i4 = tid + k * APB;
                const float4 v = __ldcs(cp4 + i4);
                const float m = s_mask[i4 / V4PA];
                const float s = neg_term(v.x) + neg_term(v.y)
                              + neg_term(v.z) + neg_term(v.w);
                cls_partial = fmaf(m, s, cls_partial);
            }
        } else {
            const int n4 = nA * V4PA;
            #pragma unroll
            for (int k = 0; k < V4PA; k++) {
                const int i4 = tid + k * APB;
                if (i4 < n4) {
                    const float4 v = __ldcs(cp4 + i4);
                    const float m = s_mask[i4 / V4PA];
                    const float s = neg_term(v.x) + neg_term(v.y)
                                  + neg_term(v.z) + neg_term(v.w);
                    cls_partial = fmaf(m, s, cls_partial);
                }
            }
        }
    }

    // Block reduction -> per-image double accumulators
    float cv = cls_partial;
    float rv = reg_partial;
    int   pv = pos_cnt;
    #pragma unroll
    for (int o = 16; o > 0; o >>= 1) {
        cv += __shfl_down_sync(0xFFFFFFFFu, cv, o);
        rv += __shfl_down_sync(0xFFFFFFFFu, rv, o);
        pv += __shfl_down_sync(0xFFFFFFFFu, pv, o);
    }
    const int wid = tid >> 5;
    const int lane = tid & 31;
    if (lane == 0) { s_rc[wid] = cv; s_rr[wid] = rv; s_rp[wid] = pv; }
    __syncthreads();
    if (tid == 0) {
        float c = 0.0f, r = 0.0f;
        int p = 0;
        #pragma unroll
        for (int i = 0; i < APB / 32; i++) { c += s_rc[i]; r += s_rr[i]; p += s_rp[i]; }
        atomicAdd(&g_cls_sum[b], (double)c);
        atomicAdd(&g_reg_sum[b], (double)r);
        if (p) atomicAdd(&g_num_pos[b], p);
    }
}

__global__ void fl_finalize_kernel(float* __restrict__ out) {
    if (threadIdx.x == 0) {
        double cl = 0.0, rl = 0.0;
        #pragma unroll
        for (int b = 0; b < B; b++) {
            const int np = g_num_pos[b];
            const double d = (np < 1) ? 1.0 : (double)np;
            cl += g_cls_sum[b] / d;
            if (np > 0) rl += g_reg_sum[b] / (4.0 * d);
        }
        out[0] = (float)(cl / (double)B);
        out[1] = (float)(rl / (double)B);
    }
}

extern "C" void kernel_launch(void* const* d_in, const int* in_sizes, int n_in,
                              void* d_out, int out_size) {
    const float* cls = nullptr;
    const float* reg = nullptr;
    const float* anc = nullptr;
    const float* ann = nullptr;
    for (int i = 0; i < n_in; i++) {
        switch (in_sizes[i]) {
            case B * A * C:  cls = (const float*)d_in[i]; break;  // 64,000,000
            case B * A * 4:  reg = (const float*)d_in[i]; break;  //  3,200,000
            case A * 4:      anc = (const float*)d_in[i]; break;  //    400,000
            case B * M * 6:  ann = (const float*)d_in[i]; break;  //      1,536
            default: break;
        }
    }
    float* out = (float*)d_out;

    fl_init_kernel<<<1, 32>>>();
    dim3 grid(NTILES, B);
    fl_main_kernel<<<grid, APB>>>(cls, reg, anc, ann);
    fl_finalize_kernel<<<1, 32>>>(out);
}